// round 8
// baseline (speedup 1.0000x reference)
#include <cuda_runtime.h>
#include <cuda_bf16.h>
#include <cstdint>

#define NMAX 512
#define DDIM 128
#define TA 4
#define MARGIN_F 0.1f
#define THREADS 1024
#define NW (THREADS / 32)

// Global accumulators (zero at load; last block resets each call so graph
// replays stay deterministic).
__device__ float        g_sum;
__device__ int          g_cnt;
__device__ unsigned int g_done;

union U2 { unsigned long long u; float2 f; };

// Packed dual-FMA (sm_10x): d.lo += a.lo*b.lo ; d.hi += a.hi*b.hi
__device__ __forceinline__ void ffma2(unsigned long long& d,
                                      unsigned long long a,
                                      unsigned long long b) {
    asm("fma.rn.f32x2 %0, %1, %2, %0;" : "+l"(d) : "l"(a), "l"(b));
}

__global__ __launch_bounds__(THREADS) void fused_triplet_kernel(
    const float* __restrict__ emb,
    const int*   __restrict__ labels_raw,
    float*       __restrict__ out,
    int n, int nblocks) {

    __shared__ __align__(16) float s_anchor[TA][DDIM];
    __shared__ float s_sim[TA][NMAX];
    __shared__ int   s_lab[NMAX];
    __shared__ short s_pos[TA][NMAX];
    __shared__ int   s_npos[TA];
    __shared__ int   s_oddor;
    __shared__ float s_bsum;
    __shared__ int   s_bcnt;

    const int t    = threadIdx.x;
    const int wid  = t >> 5;
    const int lane = t & 31;
    const int a0   = blockIdx.x * TA;

    if (t == 0) { s_oddor = 0; s_bsum = 0.0f; s_bcnt = 0; }
    if (t < TA) s_npos[t] = 0;
    __syncthreads();

    // --- labels dtype detect (int32 vs int64): OR of odd int32 words ---
    {
        int oddacc = 0;
        for (int j = t; j < n; j += THREADS)
            if (j & 1) oddacc |= labels_raw[j];
        #pragma unroll
        for (int o = 16; o > 0; o >>= 1)
            oddacc |= __shfl_xor_sync(0xffffffffu, oddacc, o);
        if (lane == 0 && oddacc) atomicOr(&s_oddor, oddacc);
    }

    // --- stage anchor rows into smem (raw) ---
    for (int i = t; i < TA * DDIM; i += THREADS) {
        int ar = i / DDIM, c = i % DDIM;
        int a = a0 + ar;
        s_anchor[ar][c] = (a < n) ? emb[(size_t)a * DDIM + c] : 1.0f;
    }
    __syncthreads();
    const bool is_i32 = (s_oddor != 0);

    // labels -> smem (needed only after the sim barrier below)
    for (int j = t; j < n; j += THREADS)
        s_lab[j] = is_i32 ? labels_raw[j] : labels_raw[2 * j];

    // --- per-lane anchor fragments (dims 4*lane .. 4*lane+3), 16B packed ---
    ulonglong2 A[TA];
    #pragma unroll
    for (int ar = 0; ar < TA; ar++)
        A[ar] = ((const ulonglong2*)s_anchor[ar])[lane];

    // anchor inverse norms (every warp computes redundantly; deterministic)
    float ainv0, ainv1, ainv2, ainv3;
    {
        float ai[TA];
        #pragma unroll
        for (int ar = 0; ar < TA; ar++) {
            unsigned long long s2 = 0ull;
            ffma2(s2, A[ar].x, A[ar].x);
            ffma2(s2, A[ar].y, A[ar].y);
            U2 u; u.u = s2;
            float v = u.f.x + u.f.y;
            #pragma unroll
            for (int o = 16; o > 0; o >>= 1)
                v += __shfl_xor_sync(0xffffffffu, v, o);
            ai[ar] = 1.0f / sqrtf(v);
        }
        ainv0 = ai[0]; ainv1 = ai[1]; ainv2 = ai[2]; ainv3 = ai[3];
    }

    // --- main pass: warp-per-row, coalesced LDG, zero-LDS dot products ---
    {
        const ulonglong2* embp = (const ulonglong2*)emb;   // 16B units
        for (int r = wid; r < n; r += NW) {
            // row r: 128 floats = 32 x 16B units; lane owns unit `lane`
            ulonglong2 e = embp[(size_t)r * (DDIM / 4) + lane];

            unsigned long long accN = 0ull;
            unsigned long long acc[TA];
            #pragma unroll
            for (int ar = 0; ar < TA; ar++) acc[ar] = 0ull;

            ffma2(accN, e.x, e.x);
            ffma2(accN, e.y, e.y);
            #pragma unroll
            for (int ar = 0; ar < TA; ar++) {
                ffma2(acc[ar], e.x, A[ar].x);
                ffma2(acc[ar], e.y, A[ar].y);
            }

            U2 un; un.u = accN;
            U2 u0; u0.u = acc[0];
            U2 u1; u1.u = acc[1];
            U2 u2; u2.u = acc[2];
            U2 u3; u3.u = acc[3];
            float nrm = un.f.x + un.f.y;
            float d0  = u0.f.x + u0.f.y;
            float d1  = u1.f.x + u1.f.y;
            float d2  = u2.f.x + u2.f.y;
            float d3  = u3.f.x + u3.f.y;

            // interleaved butterfly reductions (5 independent chains)
            #pragma unroll
            for (int o = 16; o > 0; o >>= 1) {
                nrm += __shfl_xor_sync(0xffffffffu, nrm, o);
                d0  += __shfl_xor_sync(0xffffffffu, d0, o);
                d1  += __shfl_xor_sync(0xffffffffu, d1, o);
                d2  += __shfl_xor_sync(0xffffffffu, d2, o);
                d3  += __shfl_xor_sync(0xffffffffu, d3, o);
            }

            float jinv = rsqrtf(nrm);
            if (lane < TA) {
                float d  = (lane == 0) ? d0 : (lane == 1) ? d1
                         : (lane == 2) ? d2 : d3;
                float ai = (lane == 0) ? ainv0 : (lane == 1) ? ainv1
                         : (lane == 2) ? ainv2 : ainv3;
                s_sim[lane][r] = d * ai * jinv;
            }
        }
    }
    __syncthreads();   // sim + labels complete

    // --- build positive lists for all TA anchors in one pass ---
    int  la[TA];
    bool va[TA];
    #pragma unroll
    for (int ar = 0; ar < TA; ar++) {
        int a = a0 + ar;
        va[ar] = (a < n);
        la[ar] = va[ar] ? s_lab[a] : -1;
    }
    for (int j = t; j < n; j += THREADS) {
        int lj = s_lab[j];
        #pragma unroll
        for (int ar = 0; ar < TA; ar++) {
            if (va[ar] && lj == la[ar] && j != a0 + ar) {
                int idx = atomicAdd(&s_npos[ar], 1);
                s_pos[ar][idx] = (short)j;
            }
        }
    }
    __syncthreads();

    int npos[TA];
    #pragma unroll
    for (int ar = 0; ar < TA; ar++) npos[ar] = s_npos[ar];

    // --- negative sweep: accumulate all TA anchors per column ---
    float sum = 0.0f;
    int   cnt = 0;
    for (int nj = t; nj < n; nj += THREADS) {
        int lj = s_lab[nj];
        #pragma unroll
        for (int ar = 0; ar < TA; ar++) {
            if (va[ar] && lj != la[ar]) {
                float sn = s_sim[ar][nj] + MARGIN_F;
                int np = npos[ar];
                for (int pi = 0; pi < np; pi++) {
                    float v = sn - s_sim[ar][s_pos[ar][pi]];
                    float r = fmaxf(v, 0.0f);
                    sum += r;
                    cnt += (r > 1e-16f) ? 1 : 0;
                }
            }
        }
    }

    // --- block reduce: warp shfl + smem atomics ---
    #pragma unroll
    for (int o = 16; o > 0; o >>= 1) {
        sum += __shfl_xor_sync(0xffffffffu, sum, o);
        cnt += __shfl_xor_sync(0xffffffffu, cnt, o);
    }
    if (lane == 0) {
        atomicAdd(&s_bsum, sum);
        atomicAdd(&s_bcnt, cnt);
    }
    __syncthreads();

    // --- global reduce + last-block finalize ---
    if (t == 0) {
        atomicAdd(&g_sum, s_bsum);
        atomicAdd(&g_cnt, s_bcnt);
        __threadfence();
        unsigned int d = atomicAdd(&g_done, 1u);
        if (d == (unsigned int)(nblocks - 1)) {
            float fs = g_sum;
            float fc = (float)g_cnt;
            out[0] = fs / (fc + 1e-16f);
            g_sum  = 0.0f;
            g_cnt  = 0;
            __threadfence();
            g_done = 0u;
        }
    }
}

extern "C" void kernel_launch(void* const* d_in, const int* in_sizes, int n_in,
                              void* d_out, int out_size) {
    const float* emb    = (const float*)d_in[0];
    const int*   labels = (const int*)d_in[1];
    float*       out    = (float*)d_out;

    int n = in_sizes[1];
    if (n > NMAX) n = NMAX;

    int nblocks = (n + TA - 1) / TA;
    fused_triplet_kernel<<<nblocks, THREADS>>>(emb, labels, out, n, nblocks);
}

// round 9
// speedup vs baseline: 2.1348x; 2.1348x over previous
#include <cuda_runtime.h>
#include <cuda_bf16.h>
#include <cstdint>

#define NMAX 512
#define DDIM 128
#define TA 4
#define MARGIN_F 0.1f
#define THREADS 512
#define NW (THREADS / 32)
#define SIMP (NMAX + 4)   // padded sim stride (bank-conflict-free stores)

// Global accumulators (zero at load; last block resets each call so graph
// replays stay deterministic).
__device__ float        g_sum;
__device__ int          g_cnt;
__device__ unsigned int g_done;

union U2 { unsigned long long u; float2 f; };

// Packed dual-FMA (sm_10x): d.lo += a.lo*b.lo ; d.hi += a.hi*b.hi
__device__ __forceinline__ void ffma2(unsigned long long& d,
                                      unsigned long long a,
                                      unsigned long long b) {
    asm("fma.rn.f32x2 %0, %1, %2, %0;" : "+l"(d) : "l"(a), "l"(b));
}

__global__ __launch_bounds__(THREADS, 1) void fused_triplet_kernel(
    const float* __restrict__ emb,
    const int*   __restrict__ labels_raw,
    float*       __restrict__ out,
    int n, int nblocks) {

    __shared__ __align__(16) float s_anchor[TA][DDIM];
    __shared__ float s_sim[TA][SIMP];
    __shared__ int   s_lab[NMAX];
    __shared__ short s_pos[TA][NMAX];
    __shared__ int   s_npos[TA];
    __shared__ int   s_oddor;
    __shared__ float s_bsum;
    __shared__ int   s_bcnt;

    const int t    = threadIdx.x;
    const int wid  = t >> 5;
    const int lane = t & 31;
    const int q    = lane >> 3;   // sub-row within warp (0..3)
    const int p    = lane & 7;    // unit-group position (0..7)
    const int a0   = blockIdx.x * TA;

    if (t == 0) { s_oddor = 0; s_bsum = 0.0f; s_bcnt = 0; }
    if (t < TA) s_npos[t] = 0;
    __syncthreads();

    // --- labels dtype detect (int32 vs int64): OR of odd int32 words ---
    {
        int oddacc = 0;
        for (int j = t; j < n; j += THREADS)
            if (j & 1) oddacc |= labels_raw[j];
        #pragma unroll
        for (int o = 16; o > 0; o >>= 1)
            oddacc |= __shfl_xor_sync(0xffffffffu, oddacc, o);
        if (lane == 0 && oddacc) atomicOr(&s_oddor, oddacc);
    }

    // --- stage anchor rows into smem (raw) ---
    for (int i = t; i < TA * DDIM; i += THREADS) {
        int ar = i / DDIM, c = i % DDIM;
        int a = a0 + ar;
        s_anchor[ar][c] = (a < n) ? emb[(size_t)a * DDIM + c] : 1.0f;
    }
    __syncthreads();
    const bool is_i32 = (s_oddor != 0);

    // labels -> smem (consumed after the barrier below)
    for (int j = t; j < n; j += THREADS)
        s_lab[j] = is_i32 ? labels_raw[j] : labels_raw[2 * j];

    // --- register-resident anchor fragments: anchor ar, units p+8k ---
    ulonglong2 A[TA][4];
    #pragma unroll
    for (int ar = 0; ar < TA; ar++)
        #pragma unroll
        for (int k = 0; k < 4; k++)
            A[ar][k] = ((const ulonglong2*)s_anchor[ar])[p + 8 * k];

    // anchor inverse norms: 8-lane butterfly (values replicated across groups)
    float ainv0, ainv1, ainv2, ainv3;
    {
        float ai[TA];
        #pragma unroll
        for (int ar = 0; ar < TA; ar++) {
            unsigned long long s2 = 0ull;
            #pragma unroll
            for (int k = 0; k < 4; k++) {
                ffma2(s2, A[ar][k].x, A[ar][k].x);
                ffma2(s2, A[ar][k].y, A[ar][k].y);
            }
            U2 u; u.u = s2;
            float v = u.f.x + u.f.y;
            #pragma unroll
            for (int o = 4; o > 0; o >>= 1)
                v += __shfl_xor_sync(0xffffffffu, v, o);
            ai[ar] = 1.0f / sqrtf(v);
        }
        ainv0 = ai[0]; ainv1 = ai[1]; ainv2 = ai[2]; ainv3 = ai[3];
    }

    // --- main pass: 4 rows/warp, 8 lanes/row, coalesced LDG, depth-3 reduce ---
    {
        const ulonglong2* embp = (const ulonglong2*)emb;   // 16B units, 32/row
        for (int rb = wid * 4; rb < n; rb += NW * 4) {
            const int row = rb + q;
            const bool rok = (row < n);
            const ulonglong2* rp = embp + (size_t)row * (DDIM / 4);

            ulonglong2 E[4];
            #pragma unroll
            for (int k = 0; k < 4; k++) {
                if (rok) E[k] = rp[p + 8 * k];
                else     { E[k].x = 0ull; E[k].y = 0ull; }
            }

            unsigned long long accN = 0ull;
            unsigned long long acc[TA];
            #pragma unroll
            for (int ar = 0; ar < TA; ar++) acc[ar] = 0ull;

            #pragma unroll
            for (int k = 0; k < 4; k++) {
                ffma2(accN, E[k].x, E[k].x);
                ffma2(accN, E[k].y, E[k].y);
                #pragma unroll
                for (int ar = 0; ar < TA; ar++) {
                    ffma2(acc[ar], E[k].x, A[ar][k].x);
                    ffma2(acc[ar], E[k].y, A[ar][k].y);
                }
            }

            U2 un; un.u = accN;
            U2 u0; u0.u = acc[0];
            U2 u1; u1.u = acc[1];
            U2 u2; u2.u = acc[2];
            U2 u3; u3.u = acc[3];
            float nrm = un.f.x + un.f.y;
            float d0  = u0.f.x + u0.f.y;
            float d1  = u1.f.x + u1.f.y;
            float d2  = u2.f.x + u2.f.y;
            float d3  = u3.f.x + u3.f.y;

            // depth-3 butterfly within each 8-lane group (5 chains interleaved)
            #pragma unroll
            for (int o = 4; o > 0; o >>= 1) {
                nrm += __shfl_xor_sync(0xffffffffu, nrm, o);
                d0  += __shfl_xor_sync(0xffffffffu, d0, o);
                d1  += __shfl_xor_sync(0xffffffffu, d1, o);
                d2  += __shfl_xor_sync(0xffffffffu, d2, o);
                d3  += __shfl_xor_sync(0xffffffffu, d3, o);
            }

            float jinv = rsqrtf(nrm);
            if (rok && p < TA) {
                float d  = (p == 0) ? d0 : (p == 1) ? d1
                         : (p == 2) ? d2 : d3;
                float ai = (p == 0) ? ainv0 : (p == 1) ? ainv1
                         : (p == 2) ? ainv2 : ainv3;
                s_sim[p][row] = d * ai * jinv;
            }
        }
    }
    __syncthreads();   // sim + labels complete

    // --- build positive lists for all TA anchors in one pass ---
    int  la[TA];
    bool va[TA];
    #pragma unroll
    for (int ar = 0; ar < TA; ar++) {
        int a = a0 + ar;
        va[ar] = (a < n);
        la[ar] = va[ar] ? s_lab[a] : -1;
    }
    for (int j = t; j < n; j += THREADS) {
        int lj = s_lab[j];
        #pragma unroll
        for (int ar = 0; ar < TA; ar++) {
            if (va[ar] && lj == la[ar] && j != a0 + ar) {
                int idx = atomicAdd(&s_npos[ar], 1);
                s_pos[ar][idx] = (short)j;
            }
        }
    }
    __syncthreads();

    int npos[TA];
    #pragma unroll
    for (int ar = 0; ar < TA; ar++) npos[ar] = s_npos[ar];

    // --- negative sweep: accumulate all TA anchors per column ---
    float sum = 0.0f;
    int   cnt = 0;
    for (int nj = t; nj < n; nj += THREADS) {
        int lj = s_lab[nj];
        #pragma unroll
        for (int ar = 0; ar < TA; ar++) {
            if (va[ar] && lj != la[ar]) {
                float sn = s_sim[ar][nj] + MARGIN_F;
                int np = npos[ar];
                for (int pi = 0; pi < np; pi++) {
                    float v = sn - s_sim[ar][s_pos[ar][pi]];
                    float r = fmaxf(v, 0.0f);
                    sum += r;
                    cnt += (r > 1e-16f) ? 1 : 0;
                }
            }
        }
    }

    // --- block reduce: warp shfl + smem atomics ---
    #pragma unroll
    for (int o = 16; o > 0; o >>= 1) {
        sum += __shfl_xor_sync(0xffffffffu, sum, o);
        cnt += __shfl_xor_sync(0xffffffffu, cnt, o);
    }
    if (lane == 0) {
        atomicAdd(&s_bsum, sum);
        atomicAdd(&s_bcnt, cnt);
    }
    __syncthreads();

    // --- global reduce + last-block finalize ---
    if (t == 0) {
        atomicAdd(&g_sum, s_bsum);
        atomicAdd(&g_cnt, s_bcnt);
        __threadfence();
        unsigned int d = atomicAdd(&g_done, 1u);
        if (d == (unsigned int)(nblocks - 1)) {
            float fs = g_sum;
            float fc = (float)g_cnt;
            out[0] = fs / (fc + 1e-16f);
            g_sum  = 0.0f;
            g_cnt  = 0;
            __threadfence();
            g_done = 0u;
        }
    }
}

extern "C" void kernel_launch(void* const* d_in, const int* in_sizes, int n_in,
                              void* d_out, int out_size) {
    const float* emb    = (const float*)d_in[0];
    const int*   labels = (const int*)d_in[1];
    float*       out    = (float*)d_out;

    int n = in_sizes[1];
    if (n > NMAX) n = NMAX;

    int nblocks = (n + TA - 1) / TA;
    fused_triplet_kernel<<<nblocks, THREADS>>>(emb, labels, out, n, nblocks);
}

// round 10
// speedup vs baseline: 2.1591x; 1.0114x over previous
#include <cuda_runtime.h>
#include <cuda_bf16.h>
#include <cstdint>

#define NMAX 512
#define DDIM 128
#define TA 4
#define MARGIN_F 0.1f
#define THREADS 512
#define NW (THREADS / 32)
#define SIMP (NMAX + 4)   // padded sim stride

// Global accumulators (zero at load; last block resets each call so graph
// replays stay deterministic).
__device__ float        g_sum;
__device__ int          g_cnt;
__device__ unsigned int g_done;

union U2 { unsigned long long u; float2 f; };

// Packed dual-FMA (sm_10x): d.lo += a.lo*b.lo ; d.hi += a.hi*b.hi
__device__ __forceinline__ void ffma2(unsigned long long& d,
                                      unsigned long long a,
                                      unsigned long long b) {
    asm("fma.rn.f32x2 %0, %1, %2, %0;" : "+l"(d) : "l"(a), "l"(b));
}

__global__ __launch_bounds__(THREADS, 1) void fused_triplet_kernel(
    const float* __restrict__ emb,
    const int*   __restrict__ labels_raw,
    float*       __restrict__ out,
    int n, int nblocks) {

    __shared__ float s_sim[TA][SIMP];
    __shared__ int   s_lab[NMAX];
    __shared__ short s_pos[TA][NMAX];
    __shared__ int   s_npos[TA];
    __shared__ int   s_oddor;
    __shared__ float s_bsum;
    __shared__ int   s_bcnt;

    const int t    = threadIdx.x;
    const int wid  = t >> 5;
    const int lane = t & 31;
    const int q    = lane >> 3;   // sub-row within warp (0..3)
    const int p    = lane & 7;    // unit-group position (0..7)
    const int a0   = blockIdx.x * TA;

    // --- anchor fragments: direct LDG, issued first (16 independent loads;
    //     each is one 128B line broadcast across the 4 lane-groups) ---
    const ulonglong2* embp = (const ulonglong2*)emb;   // 16B units, 32/row
    ulonglong2 A[TA][4];
    #pragma unroll
    for (int ar = 0; ar < TA; ar++) {
        int a = a0 + ar;
        if (a >= n) a = 0;                     // clamped; guarded by va later
        #pragma unroll
        for (int k = 0; k < 4; k++)
            A[ar][k] = __ldg(embp + (size_t)a * (DDIM / 4) + p + 8 * k);
    }

    // --- labels word t (single load; feeds both detection and s_lab) ---
    int wlab = (t < n) ? labels_raw[t] : 0;

    if (t == 0) { s_oddor = 0; s_bsum = 0.0f; s_bcnt = 0; }
    if (t < TA) s_npos[t] = 0;

    // dtype detect: OR of odd words (int64 -> hi words all zero)
    {
        int oddacc = (t & 1) ? wlab : 0;
        #pragma unroll
        for (int o = 16; o > 0; o >>= 1)
            oddacc |= __shfl_xor_sync(0xffffffffu, oddacc, o);
        if (lane == 0 && oddacc) atomicOr(&s_oddor, oddacc);
    }

    // anchor inverse norms: 3-level 8-lane butterfly (replicated across groups)
    float ainv0, ainv1, ainv2, ainv3;
    {
        float ai[TA];
        #pragma unroll
        for (int ar = 0; ar < TA; ar++) {
            unsigned long long s2 = 0ull;
            #pragma unroll
            for (int k = 0; k < 4; k++) {
                ffma2(s2, A[ar][k].x, A[ar][k].x);
                ffma2(s2, A[ar][k].y, A[ar][k].y);
            }
            U2 u; u.u = s2;
            float v = u.f.x + u.f.y;
            #pragma unroll
            for (int o = 4; o > 0; o >>= 1)
                v += __shfl_xor_sync(0xffffffffu, v, o);
            ai[ar] = 1.0f / sqrtf(v);
        }
        ainv0 = ai[0]; ainv1 = ai[1]; ainv2 = ai[2]; ainv3 = ai[3];
    }

    __syncthreads();                  // s_oddor ready
    const bool is_i32 = (s_oddor != 0);
    if (t < n)
        s_lab[t] = is_i32 ? wlab : labels_raw[2 * t];

    // --- main pass: 4 rows/warp, 8 lanes/row ---
    if (n == NMAX) {
        // fast path: compile-time trip count -> front-batched LDGs, high MLP
        #pragma unroll
        for (int it = 0; it < NMAX / (NW * 4); it++) {
            const int row = wid * 4 + q + it * (NW * 4);
            const ulonglong2* rp = embp + (size_t)row * (DDIM / 4);

            ulonglong2 E[4];
            #pragma unroll
            for (int k = 0; k < 4; k++) E[k] = rp[p + 8 * k];

            unsigned long long accN = 0ull, acc0 = 0ull, acc1 = 0ull,
                               acc2 = 0ull, acc3 = 0ull;
            #pragma unroll
            for (int k = 0; k < 4; k++) {
                ffma2(accN, E[k].x, E[k].x);
                ffma2(accN, E[k].y, E[k].y);
                ffma2(acc0, E[k].x, A[0][k].x);
                ffma2(acc0, E[k].y, A[0][k].y);
                ffma2(acc1, E[k].x, A[1][k].x);
                ffma2(acc1, E[k].y, A[1][k].y);
                ffma2(acc2, E[k].x, A[2][k].x);
                ffma2(acc2, E[k].y, A[2][k].y);
                ffma2(acc3, E[k].x, A[3][k].x);
                ffma2(acc3, E[k].y, A[3][k].y);
            }

            U2 un; un.u = accN;
            U2 u0; u0.u = acc0;
            U2 u1; u1.u = acc1;
            U2 u2; u2.u = acc2;
            U2 u3; u3.u = acc3;
            float nrm = un.f.x + un.f.y;
            float d0  = u0.f.x + u0.f.y;
            float d1  = u1.f.x + u1.f.y;
            float d2  = u2.f.x + u2.f.y;
            float d3  = u3.f.x + u3.f.y;

            #pragma unroll
            for (int o = 4; o > 0; o >>= 1) {
                nrm += __shfl_xor_sync(0xffffffffu, nrm, o);
                d0  += __shfl_xor_sync(0xffffffffu, d0, o);
                d1  += __shfl_xor_sync(0xffffffffu, d1, o);
                d2  += __shfl_xor_sync(0xffffffffu, d2, o);
                d3  += __shfl_xor_sync(0xffffffffu, d3, o);
            }

            float jinv = rsqrtf(nrm);
            if (p < TA) {
                float d  = (p == 0) ? d0 : (p == 1) ? d1 : (p == 2) ? d2 : d3;
                float ai = (p == 0) ? ainv0 : (p == 1) ? ainv1
                         : (p == 2) ? ainv2 : ainv3;
                s_sim[p][row] = d * ai * jinv;
            }
        }
    } else {
        // general path (n < NMAX)
        for (int rb = wid * 4; rb < n; rb += NW * 4) {
            const int row = rb + q;
            const bool rok = (row < n);
            const ulonglong2* rp = embp + (size_t)row * (DDIM / 4);

            ulonglong2 E[4];
            #pragma unroll
            for (int k = 0; k < 4; k++) {
                if (rok) E[k] = rp[p + 8 * k];
                else     { E[k].x = 0ull; E[k].y = 0ull; }
            }

            unsigned long long accN = 0ull, acc0 = 0ull, acc1 = 0ull,
                               acc2 = 0ull, acc3 = 0ull;
            #pragma unroll
            for (int k = 0; k < 4; k++) {
                ffma2(accN, E[k].x, E[k].x);
                ffma2(accN, E[k].y, E[k].y);
                ffma2(acc0, E[k].x, A[0][k].x);
                ffma2(acc0, E[k].y, A[0][k].y);
                ffma2(acc1, E[k].x, A[1][k].x);
                ffma2(acc1, E[k].y, A[1][k].y);
                ffma2(acc2, E[k].x, A[2][k].x);
                ffma2(acc2, E[k].y, A[2][k].y);
                ffma2(acc3, E[k].x, A[3][k].x);
                ffma2(acc3, E[k].y, A[3][k].y);
            }

            U2 un; un.u = accN;
            U2 u0; u0.u = acc0;
            U2 u1; u1.u = acc1;
            U2 u2; u2.u = acc2;
            U2 u3; u3.u = acc3;
            float nrm = un.f.x + un.f.y;
            float d0  = u0.f.x + u0.f.y;
            float d1  = u1.f.x + u1.f.y;
            float d2  = u2.f.x + u2.f.y;
            float d3  = u3.f.x + u3.f.y;

            #pragma unroll
            for (int o = 4; o > 0; o >>= 1) {
                nrm += __shfl_xor_sync(0xffffffffu, nrm, o);
                d0  += __shfl_xor_sync(0xffffffffu, d0, o);
                d1  += __shfl_xor_sync(0xffffffffu, d1, o);
                d2  += __shfl_xor_sync(0xffffffffu, d2, o);
                d3  += __shfl_xor_sync(0xffffffffu, d3, o);
            }

            float jinv = rsqrtf(nrm);
            if (rok && p < TA) {
                float d  = (p == 0) ? d0 : (p == 1) ? d1 : (p == 2) ? d2 : d3;
                float ai = (p == 0) ? ainv0 : (p == 1) ? ainv1
                         : (p == 2) ? ainv2 : ainv3;
                s_sim[p][row] = d * ai * jinv;
            }
        }
    }
    __syncthreads();   // sim + labels complete

    // --- build positive lists for all TA anchors in one pass ---
    int  la[TA];
    bool va[TA];
    #pragma unroll
    for (int ar = 0; ar < TA; ar++) {
        int a = a0 + ar;
        va[ar] = (a < n);
        la[ar] = va[ar] ? s_lab[a] : -1;
    }
    for (int j = t; j < n; j += THREADS) {
        int lj = s_lab[j];
        #pragma unroll
        for (int ar = 0; ar < TA; ar++) {
            if (va[ar] && lj == la[ar] && j != a0 + ar) {
                int idx = atomicAdd(&s_npos[ar], 1);
                s_pos[ar][idx] = (short)j;
            }
        }
    }
    __syncthreads();

    int npos[TA];
    #pragma unroll
    for (int ar = 0; ar < TA; ar++) npos[ar] = s_npos[ar];

    // --- negative sweep: accumulate all TA anchors per column ---
    float sum = 0.0f;
    int   cnt = 0;
    for (int nj = t; nj < n; nj += THREADS) {
        int lj = s_lab[nj];
        #pragma unroll
        for (int ar = 0; ar < TA; ar++) {
            if (va[ar] && lj != la[ar]) {
                float sn = s_sim[ar][nj] + MARGIN_F;
                int np = npos[ar];
                for (int pi = 0; pi < np; pi++) {
                    float v = sn - s_sim[ar][s_pos[ar][pi]];
                    float r = fmaxf(v, 0.0f);
                    sum += r;
                    cnt += (r > 1e-16f) ? 1 : 0;
                }
            }
        }
    }

    // --- block reduce: warp shfl + smem atomics ---
    #pragma unroll
    for (int o = 16; o > 0; o >>= 1) {
        sum += __shfl_xor_sync(0xffffffffu, sum, o);
        cnt += __shfl_xor_sync(0xffffffffu, cnt, o);
    }
    if (lane == 0) {
        atomicAdd(&s_bsum, sum);
        atomicAdd(&s_bcnt, cnt);
    }
    __syncthreads();

    // --- global reduce + last-block finalize ---
    if (t == 0) {
        atomicAdd(&g_sum, s_bsum);
        atomicAdd(&g_cnt, s_bcnt);
        __threadfence();
        unsigned int d = atomicAdd(&g_done, 1u);
        if (d == (unsigned int)(nblocks - 1)) {
            float fs = g_sum;
            float fc = (float)g_cnt;
            out[0] = fs / (fc + 1e-16f);
            g_sum  = 0.0f;
            g_cnt  = 0;
            __threadfence();
            g_done = 0u;
        }
    }
}

extern "C" void kernel_launch(void* const* d_in, const int* in_sizes, int n_in,
                              void* d_out, int out_size) {
    const float* emb    = (const float*)d_in[0];
    const int*   labels = (const int*)d_in[1];
    float*       out    = (float*)d_out;

    int n = in_sizes[1];
    if (n > NMAX) n = NMAX;

    int nblocks = (n + TA - 1) / TA;
    fused_triplet_kernel<<<nblocks, THREADS>>>(emb, labels, out, n, nblocks);
}